// round 11
// baseline (speedup 1.0000x reference)
#include <cuda_runtime.h>
#include <cstdint>

#define NB 8
#define NPTS 16384
#define NS 1024
#define NK 32
#define ND 64
#define NC0 67
#define MTOT (NB*NS*NK)
#define BN_EPS 1e-5f
typedef unsigned long long ull;

__device__ float g_X0[(size_t)NC0*MTOT];
__device__ float g_A [(size_t)64 *MTOT];
__device__ float g_Bf[(size_t)64 *MTOT];
__device__ float g_Y3[(size_t)128*MTOT];
__device__ float g_newxyz[NB*NS*3];
__device__ float g_sum[3*128];
__device__ float g_ssq[3*128];

struct Far0 { int v[NB]; };
__device__ __forceinline__ ull umax64(ull a, ull b){ return a>b?a:b; }
__device__ __forceinline__ ull umin64(ull a, ull b){ return a<b?a:b; }

// ---------------- FPS: one block/batch, hybrid regs + float4-SMEM ----------------
// 1024 threads: 8 points in registers (no LDS), 8 points in SMEM as float4
// (single LDS.128 per point, conflict-free interleave i*1024+tid).
#define FPS_RP 8                      // points in registers per thread
#define FPS_SP 8                      // points in SMEM per thread
#define FPS_SOFF (FPS_RP*1024)        // global index offset of SMEM half (8192)

__global__ __launch_bounds__(1024,1)
void fps_kernel(const float* __restrict__ xyz,
                float* __restrict__ newxyz, float* __restrict__ out_xyz, Far0 far0)
{
    const int b = blockIdx.x, tid = threadIdx.x;
    const int wid = tid >> 5, lane = tid & 31;
    const float* xb = xyz + (size_t)b*3*NPTS;

    extern __shared__ char smraw[];
    float4* s4 = (float4*)smraw;                    // 8192 * 16B = 128KB
    __shared__ ull s_wkey[32];
    __shared__ float s_c[3];

    // register half: points n = i*1024 + tid, i < 8
    float px[FPS_RP], py[FPS_RP], pz[FPS_RP], distR[FPS_RP], distS[FPS_SP];
#pragma unroll
    for (int i = 0; i < FPS_RP; i++) {
        int n = i*1024 + tid;
        px[i] = xb[n]; py[i] = xb[NPTS+n]; pz[i] = xb[2*NPTS+n];
        distR[i] = __int_as_float(0x7f800000);
    }
    // SMEM half: points n = 8192 + m, m = j*1024 + tid
#pragma unroll
    for (int j = 0; j < FPS_SP; j++) {
        int m = j*1024 + tid;
        int n = FPS_SOFF + m;
        s4[m] = make_float4(xb[n], xb[NPTS+n], xb[2*NPTS+n], 0.f);
        distS[j] = __int_as_float(0x7f800000);
    }
    __syncthreads();

    const int far = far0.v[b];
    float cx = xb[far], cy = xb[NPTS+far], cz = xb[2*NPTS+far];

    for (int s = 0; s < NS; s++) {
        if (tid == 0) {
            int q = (b*NS+s)*3;
            newxyz[q+0] = cx; newxyz[q+1] = cy; newxyz[q+2] = cz;
            out_xyz[(size_t)b*3*NS + s]        = cx;
            out_xyz[(size_t)b*3*NS + NS + s]   = cy;
            out_xyz[(size_t)b*3*NS + 2*NS + s] = cz;
        }
        ull mybest = 0;
        // SMEM half (LDS.128 in flight while reg half computes)
#pragma unroll
        for (int j = 0; j < FPS_SP; j++) {
            int m = j*1024 + tid;
            float4 v = s4[m];
            float dx = v.x-cx, dy = v.y-cy, dz = v.z-cz;
            float d = __fadd_rn(__fadd_rn(__fmul_rn(dx,dx),__fmul_rn(dy,dy)),__fmul_rn(dz,dz));
            float dd = fminf(distS[j], d);
            distS[j] = dd;
            mybest = umax64(mybest,
                ((ull)__float_as_uint(dd)<<32) | (0xFFFFFFFFu - (unsigned)(FPS_SOFF+m)));
        }
        // register half
#pragma unroll
        for (int i = 0; i < FPS_RP; i++) {
            float dx = px[i]-cx, dy = py[i]-cy, dz = pz[i]-cz;
            float d = __fadd_rn(__fadd_rn(__fmul_rn(dx,dx),__fmul_rn(dy,dy)),__fmul_rn(dz,dz));
            float dd = fminf(distR[i], d);
            distR[i] = dd;
            mybest = umax64(mybest,
                ((ull)__float_as_uint(dd)<<32) | (0xFFFFFFFFu - (unsigned)(i*1024+tid)));
        }
        ull red = mybest;
#pragma unroll
        for (int off = 16; off; off >>= 1) red = umax64(red, __shfl_down_sync(~0u, red, off));
        if (lane == 0) s_wkey[wid] = red;
        __syncthreads();
        ull ctab = s_wkey[0];
#pragma unroll
        for (int w = 1; w < 32; w++) ctab = umax64(ctab, s_wkey[w]);

        if (mybest == ctab) {   // unique owner (key carries unique index)
            unsigned n = 0xFFFFFFFFu - (unsigned)ctab;
            float wx, wy, wz;
            if (n < FPS_SOFF) {
                int ii = (int)(n >> 10);
                wx = 0.f; wy = 0.f; wz = 0.f;
#pragma unroll
                for (int i = 0; i < FPS_RP; i++)
                    if (ii == i) { wx = px[i]; wy = py[i]; wz = pz[i]; }
            } else {
                float4 v = s4[n - FPS_SOFF];
                wx = v.x; wy = v.y; wz = v.z;
            }
            s_c[0] = wx; s_c[1] = wy; s_c[2] = wz;
        }
        __syncthreads();
        cx = s_c[0]; cy = s_c[1]; cz = s_c[2];
    }
}

// ---------------- kNN radix-select + grouping ----------------
__global__ __launch_bounds__(128,2)
void knn_kernel(const float* __restrict__ xyz, const float* __restrict__ points,
                const float* __restrict__ newxyz, float* __restrict__ X0)
{
    const int blk = blockIdx.x, b = blk >> 10, tid = threadIdx.x;
    const float* xb = xyz + (size_t)b*3*NPTS;
    extern __shared__ char smraw[];
    float* sdist = (float*)smraw;              // 64KB
    int*   hist  = (int*)(smraw + 65536);      // 16KB
    int*   cand  = hist + 4096;                // 8KB
    __shared__ int sel[NK];
    __shared__ int selcnt, candcnt, s_bstar, s_below;
    __shared__ int csum[128];
    __shared__ ull wred[4];
    const float cx = newxyz[blk*3+0], cy = newxyz[blk*3+1], cz = newxyz[blk*3+2];

    for (int i = tid; i < 4096; i += 128) hist[i] = 0;
    if (tid == 0) { selcnt = 0; candcnt = 0; }
    __syncthreads();
    for (int i = 0; i < 128; i++) {
        int n = i*128 + tid;
        float dx = xb[n]-cx, dy = xb[NPTS+n]-cy, dz = xb[2*NPTS+n]-cz;
        float d = dx*dx + dy*dy + dz*dz;
        sdist[n] = d;
        atomicAdd(&hist[__float_as_uint(d)>>20], 1);
    }
    __syncthreads();
    int cs = 0;
    for (int j = 0; j < 32; j++) cs += hist[tid*32+j];
    csum[tid] = cs;
    __syncthreads();
    for (int off = 1; off < 128; off <<= 1) {
        int v = csum[tid];
        int add = (tid >= off) ? csum[tid-off] : 0;
        __syncthreads();
        csum[tid] = v + add;
        __syncthreads();
    }
    int incl = csum[tid], excl = incl - cs;
    if (excl < NK && incl >= NK) {
        int acc = excl, bstar = -1;
        for (int j = 0; j < 32; j++) {
            int h = hist[tid*32+j];
            if (acc + h >= NK) { bstar = tid*32+j; break; }
            acc += h;
        }
        s_bstar = bstar; s_below = acc;
    }
    __syncthreads();
    const int bstar = s_bstar, below = s_below;
    for (int i = 0; i < 128; i++) {
        int n = i*128 + tid;
        int bin = (int)(__float_as_uint(sdist[n])>>20);
        if (bin < bstar)       { int p = atomicAdd(&selcnt,1); sel[p] = n; }
        else if (bin == bstar) { int p = atomicAdd(&candcnt,1); if (p < 2048) cand[p] = n; }
    }
    __syncthreads();
    const int r = NK - below;
    const bool fb = (candcnt > 2048);
    for (int e = 0; e < r; e++) {
        ull best = ~0ull;
        if (!fb) {
            for (int i = tid; i < candcnt; i += 128) {
                int n = cand[i];
                best = umin64(best, ((ull)__float_as_uint(sdist[n])<<32) | (unsigned)n);
            }
        } else {
            for (int i = 0; i < 128; i++) {
                int n = i*128 + tid;
                unsigned u = __float_as_uint(sdist[n]);
                if ((int)(u>>20) == bstar) best = umin64(best, ((ull)u<<32) | (unsigned)n);
            }
        }
#pragma unroll
        for (int off = 16; off; off >>= 1) best = umin64(best, __shfl_down_sync(~0u, best, off));
        if ((tid&31)==0) wred[tid>>5] = best;
        __syncthreads();
        if (tid == 0) {
            best = umin64(umin64(wred[0],wred[1]), umin64(wred[2],wred[3]));
            int n = (int)(unsigned)best;
            sel[below+e] = n;
            sdist[n] = __int_as_float(0x7f800000);
        }
        __syncthreads();
    }
    const size_t mb = (size_t)blk*NK;
    const float* pb = points + (size_t)b*ND*NPTS;
    for (int t = tid; t < NC0*NK; t += 128) {
        int c = t>>5, k = t&31;
        int idx = sel[k];
        float v;
        if (c < 3) {
            float cc = (c==0)?cx:((c==1)?cy:cz);
            v = xb[(size_t)c*NPTS+idx] - cc;
        } else v = pb[(size_t)(c-3)*NPTS+idx];
        X0[(size_t)c*MTOT + mb + k] = v;
    }
}

// ---------------- GEMM 64(o)x128(m) tile ----------------
template <int C>
__global__ __launch_bounds__(256)
void gemm_kernel(const float* __restrict__ X, const float* __restrict__ W,
                 const float* __restrict__ bias, float* __restrict__ Y)
{
    extern __shared__ float smf[];
    float* Ws = smf;           // [C][64]
    float* Xs = smf + C*64;    // [C][128]
    const int m0 = blockIdx.x*128, ob = blockIdx.y*64;
    for (int i = threadIdx.x; i < C*64; i += 256) {
        int o = i&63, c = i>>6;
        Ws[c*64+o] = W[(size_t)(ob+o)*C + c];
    }
    for (int i = threadIdx.x; i < C*128; i += 256) {
        int c = i>>7, j = i&127;
        Xs[c*128+j] = X[(size_t)c*MTOT + m0 + j];
    }
    __syncthreads();
    const int tm = (threadIdx.x&31)*4, to = (threadIdx.x>>5)*8;
    float4 acc[8];
#pragma unroll
    for (int j = 0; j < 8; j++) acc[j] = make_float4(0.f,0.f,0.f,0.f);
#pragma unroll 4
    for (int c = 0; c < C; c++) {
        const float4 xv = *(const float4*)(Xs + c*128 + tm);
        const float4 wa = *(const float4*)(Ws + c*64 + to);
        const float4 wb = *(const float4*)(Ws + c*64 + to + 4);
        const float w[8] = {wa.x,wa.y,wa.z,wa.w,wb.x,wb.y,wb.z,wb.w};
#pragma unroll
        for (int j = 0; j < 8; j++) {
            acc[j].x = fmaf(w[j], xv.x, acc[j].x);
            acc[j].y = fmaf(w[j], xv.y, acc[j].y);
            acc[j].z = fmaf(w[j], xv.z, acc[j].z);
            acc[j].w = fmaf(w[j], xv.w, acc[j].w);
        }
    }
#pragma unroll
    for (int j = 0; j < 8; j++) {
        int row = ob + to + j;
        float bo = bias[row];
        float4 rv = acc[j];
        rv.x += bo; rv.y += bo; rv.z += bo; rv.w += bo;
        *(float4*)(Y + (size_t)row*MTOT + m0 + tm) = rv;
    }
}

// ---------------- BN stats / apply / maxpool ----------------
__global__ void zero_stats_kernel(float* sum, float* ssq)
{
    int i = threadIdx.x;
    if (i < 3*128) { sum[i] = 0.f; ssq[i] = 0.f; }
}

__global__ __launch_bounds__(256)
void stats_kernel(const float* __restrict__ Y, float* __restrict__ sum, float* __restrict__ ssq)
{
    const int o = blockIdx.x >> 5;
    const int chunk = (blockIdx.x & 31) << 13;
    const float* p = Y + (size_t)o*MTOT + chunk;
    float s = 0.f, q = 0.f;
    for (int i = threadIdx.x; i < 8192; i += 256) {
        float v = __ldg(p+i);
        s += v; q += v*v;
    }
#pragma unroll
    for (int off = 16; off; off >>= 1) {
        s += __shfl_down_sync(~0u, s, off);
        q += __shfl_down_sync(~0u, q, off);
    }
    __shared__ float ws[8], wq[8];
    if ((threadIdx.x&31)==0) { ws[threadIdx.x>>5] = s; wq[threadIdx.x>>5] = q; }
    __syncthreads();
    if (threadIdx.x < 8) {
        s = ws[threadIdx.x]; q = wq[threadIdx.x];
#pragma unroll
        for (int off = 4; off; off >>= 1) {
            s += __shfl_down_sync(0xFFu, s, off);
            q += __shfl_down_sync(0xFFu, q, off);
        }
        if (threadIdx.x == 0) { atomicAdd(&sum[o], s); atomicAdd(&ssq[o], q); }
    }
}

__global__ __launch_bounds__(256)
void bn_relu_kernel(float* __restrict__ Y, const float* __restrict__ sum,
                    const float* __restrict__ ssq, const float* __restrict__ gamma,
                    const float* __restrict__ beta)
{
    const int o = blockIdx.x >> 8;
    const int base = (blockIdx.x & 255)*1024 + threadIdx.x*4;
    const float inv = 1.0f/(float)MTOT;
    float mean = sum[o]*inv;
    float var  = ssq[o]*inv - mean*mean;
    float sc = gamma[o]*rsqrtf(var + BN_EPS);
    float sh = beta[o] - sc*mean;
    float4* p = (float4*)(Y + (size_t)o*MTOT + base);
    float4 v = *p;
    v.x = fmaxf(fmaf(sc,v.x,sh),0.f); v.y = fmaxf(fmaf(sc,v.y,sh),0.f);
    v.z = fmaxf(fmaf(sc,v.z,sh),0.f); v.w = fmaxf(fmaf(sc,v.w,sh),0.f);
    *p = v;
}

__global__ __launch_bounds__(256)
void maxpool_kernel(const float* __restrict__ X, float* __restrict__ out)
{
    const int j = blockIdx.x*256 + threadIdx.x;
    const int b = j >> 17, o = (j >> 10) & 127, s = j & 1023;
    const float4* p = (const float4*)(X + (size_t)o*MTOT + ((size_t)(b*NS+s)<<5));
    float m = -__int_as_float(0x7f800000);
#pragma unroll
    for (int i = 0; i < 8; i++) {
        float4 v = p[i];
        m = fmaxf(m, fmaxf(fmaxf(v.x,v.y), fmaxf(v.z,v.w)));
    }
    out[j] = m;
}

// ---------------- host threefry for far0 ----------------
static inline uint32_t rotl32(uint32_t x, int d){ return (x<<d)|(x>>(32-d)); }
static void tf2x32(uint32_t k0, uint32_t k1, uint32_t x0, uint32_t x1,
                   uint32_t* o0, uint32_t* o1)
{
    uint32_t ks[3] = { k0, k1, k0^k1^0x1BD11BDAu };
    x0 += ks[0]; x1 += ks[1];
    static const int R[2][4] = { {13,15,26,6}, {17,29,16,24} };
    for (int g = 0; g < 5; g++) {
        const int* r = R[g&1];
        for (int i = 0; i < 4; i++) { x0 += x1; x1 = rotl32(x1, r[i]); x1 ^= x0; }
        x0 += ks[(g+1)%3];
        x1 += ks[(g+2)%3] + (uint32_t)(g+1);
    }
    *o0 = x0; *o1 = x1;
}
static void compute_far0(int* far)
{
    // jax.random.randint(key(42),(8,),0,16384), threefry_partitionable:
    // k2 = block(key,(0,1)); bits[i] = o0^o1 of block(k2,(0,i)); far = bits & 16383
    uint32_t ka, kb;
    tf2x32(0u, 42u, 0u, 1u, &ka, &kb);
    for (int i = 0; i < NB; i++) {
        uint32_t o0, o1;
        tf2x32(ka, kb, 0u, (uint32_t)i, &o0, &o1);
        far[i] = (int)((o0 ^ o1) & (NPTS - 1));
    }
}

extern "C" void kernel_launch(void* const* d_in, const int* in_sizes, int n_in,
                              void* d_out, int out_size)
{
    const float* xyz    = (const float*)d_in[0];
    const float* points = (const float*)d_in[1];
    const float* w0 = (const float*)d_in[2];
    const float* b0 = (const float*)d_in[3];
    const float* g0 = (const float*)d_in[4];
    const float* be0= (const float*)d_in[5];
    const float* w1 = (const float*)d_in[6];
    const float* b1 = (const float*)d_in[7];
    const float* g1 = (const float*)d_in[8];
    const float* be1= (const float*)d_in[9];
    const float* w2 = (const float*)d_in[10];
    const float* b2 = (const float*)d_in[11];
    const float* g2 = (const float*)d_in[12];
    const float* be2= (const float*)d_in[13];
    float* out = (float*)d_out;

    Far0 f; compute_far0(f.v);

    float *X0,*A,*Bf,*Y3,*nxyz,*sum,*ssq;
    cudaGetSymbolAddress((void**)&X0, g_X0);
    cudaGetSymbolAddress((void**)&A,  g_A);
    cudaGetSymbolAddress((void**)&Bf, g_Bf);
    cudaGetSymbolAddress((void**)&Y3, g_Y3);
    cudaGetSymbolAddress((void**)&nxyz, g_newxyz);
    cudaGetSymbolAddress((void**)&sum, g_sum);
    cudaGetSymbolAddress((void**)&ssq, g_ssq);

    const int FPS_SMEM = (NPTS/2) * 16;        // 131072
    const int KNN_SMEM = 65536 + 16384 + 8192;
    const int G67_SMEM = (NC0*64 + NC0*128)*4;
    const int G64_SMEM = (64*64 + 64*128)*4;
    cudaFuncSetAttribute(fps_kernel, cudaFuncAttributeMaxDynamicSharedMemorySize, FPS_SMEM);
    cudaFuncSetAttribute(knn_kernel, cudaFuncAttributeMaxDynamicSharedMemorySize, KNN_SMEM);
    cudaFuncSetAttribute(gemm_kernel<NC0>, cudaFuncAttributeMaxDynamicSharedMemorySize, G67_SMEM);
    cudaFuncSetAttribute(gemm_kernel<64>,  cudaFuncAttributeMaxDynamicSharedMemorySize, G64_SMEM);

    fps_kernel<<<NB, 1024, FPS_SMEM>>>(xyz, nxyz, out, f);
    knn_kernel<<<NB*NS, 128, KNN_SMEM>>>(xyz, points, nxyz, X0);

    zero_stats_kernel<<<1, 512>>>(sum, ssq);

    gemm_kernel<NC0><<<dim3(MTOT/128,1), 256, G67_SMEM>>>(X0, w0, b0, A);
    stats_kernel<<<64*32, 256>>>(A, sum+0, ssq+0);
    bn_relu_kernel<<<64*256, 256>>>(A, sum+0, ssq+0, g0, be0);

    gemm_kernel<64><<<dim3(MTOT/128,1), 256, G64_SMEM>>>(A, w1, b1, Bf);
    stats_kernel<<<64*32, 256>>>(Bf, sum+64, ssq+64);
    bn_relu_kernel<<<64*256, 256>>>(Bf, sum+64, ssq+64, g1, be1);

    gemm_kernel<64><<<dim3(MTOT/128,2), 256, G64_SMEM>>>(Bf, w2, b2, Y3);
    stats_kernel<<<128*32, 256>>>(Y3, sum+128, ssq+128);
    bn_relu_kernel<<<128*256, 256>>>(Y3, sum+128, ssq+128, g2, be2);

    maxpool_kernel<<<(NB*128*NS)/256, 256>>>(Y3, out + NB*3*NS);
}

// round 13
// speedup vs baseline: 1.0887x; 1.0887x over previous
#include <cuda_runtime.h>
#include <cstdint>

#define NB 8
#define NPTS 16384
#define NS 1024
#define NK 32
#define ND 64
#define NC0 67
#define MTOT (NB*NS*NK)
#define BN_EPS 1e-5f
typedef unsigned long long ull;

__device__ float g_X0[(size_t)NC0*MTOT];
__device__ float g_A [(size_t)64 *MTOT];
__device__ float g_Bf[(size_t)64 *MTOT];
__device__ float g_Y3[(size_t)128*MTOT];
__device__ float g_newxyz[NB*NS*3];
__device__ float g_sum[3*128];
__device__ float g_ssq[3*128];
// spatially sorted copies for FPS
__device__ float g_sx[NB*NPTS];
__device__ float g_sy[NB*NPTS];
__device__ float g_sz[NB*NPTS];
__device__ unsigned short g_sidx[NB*NPTS];

struct Far0 { int v[NB]; };
__device__ __forceinline__ ull umax64(ull a, ull b){ return a>b?a:b; }
__device__ __forceinline__ ull umin64(ull a, ull b){ return a<b?a:b; }

// ---------------- spatial counting sort (per batch) ----------------
__device__ __forceinline__ int morton4(int x, int y, int z){
    int m = 0;
#pragma unroll
    for (int i = 0; i < 4; i++)
        m |= (((x>>i)&1) << (3*i)) | (((y>>i)&1) << (3*i+1)) | (((z>>i)&1) << (3*i+2));
    return m;
}
__device__ __forceinline__ int cell_of(float x, float y, float z){
    int cx = (int)floorf((x + 4.f) * 2.f);
    int cy = (int)floorf((y + 4.f) * 2.f);
    int cz = (int)floorf((z + 4.f) * 2.f);
    cx = cx < 0 ? 0 : (cx > 15 ? 15 : cx);
    cy = cy < 0 ? 0 : (cy > 15 ? 15 : cy);
    cz = cz < 0 ? 0 : (cz > 15 ? 15 : cz);
    return morton4(cx, cy, cz);
}

__global__ __launch_bounds__(1024,1)
void sort_kernel(const float* __restrict__ xyz)
{
    const int b = blockIdx.x, tid = threadIdx.x;
    const float* xb = xyz + (size_t)b*3*NPTS;
    __shared__ int hist[4096];
    __shared__ int part[1024];
    int c[16];

    for (int i = tid; i < 4096; i += 1024) hist[i] = 0;
    __syncthreads();
#pragma unroll
    for (int i = 0; i < 16; i++) {
        int n = i*1024 + tid;
        int cl = cell_of(xb[n], xb[NPTS+n], xb[2*NPTS+n]);
        c[i] = cl;
        atomicAdd(&hist[cl], 1);
    }
    __syncthreads();
    int psum = hist[4*tid] + hist[4*tid+1] + hist[4*tid+2] + hist[4*tid+3];
    part[tid] = psum;
    __syncthreads();
    for (int off = 1; off < 1024; off <<= 1) {
        int v = part[tid];
        int add = (tid >= off) ? part[tid-off] : 0;
        __syncthreads();
        part[tid] = v + add;
        __syncthreads();
    }
    int excl = part[tid] - psum;
#pragma unroll
    for (int j = 0; j < 4; j++) {
        int old = hist[4*tid+j];
        hist[4*tid+j] = excl;
        excl += old;
    }
    __syncthreads();
    const size_t bN = (size_t)b*NPTS;
#pragma unroll
    for (int i = 0; i < 16; i++) {
        int n = i*1024 + tid;
        float x = xb[n], y = xb[NPTS+n], z = xb[2*NPTS+n];
        int pos = atomicAdd(&hist[c[i]], 1);
        g_sx[bN+pos] = x; g_sy[bN+pos] = y; g_sz[bN+pos] = z;
        g_sidx[bN+pos] = (unsigned short)n;
    }
}

// ---------------- FPS: one block/batch, exact group-pruned ----------------
// thread t owns 16 spatially-contiguous sorted points (SMEM pad-17 planar),
// with group center+radius. Skip a group iff (|c-g|*(1-e) - r)^2*(1-e) > ub
// (ub = group's current max dist) => provably no dist in group changes.
#define FPS_PAD 17

__global__ __launch_bounds__(1024,1)
void fps_kernel(const float* __restrict__ xyz,
                float* __restrict__ newxyz, float* __restrict__ out_xyz, Far0 far0)
{
    const int b = blockIdx.x, tid = threadIdx.x;
    const int wid = tid >> 5, lane = tid & 31;
    const size_t bN = (size_t)b*NPTS;

    extern __shared__ char smraw[];
    float* sx = (float*)smraw;                         // 1024*17 floats
    float* sy = sx + 1024*FPS_PAD;
    float* sz = sy + 1024*FPS_PAD;
    __shared__ ull s_wkey[32];
    __shared__ float s_c[3];

    for (int j = tid; j < NPTS; j += 1024) {
        int slot = (j >> 4)*FPS_PAD + (j & 15);
        sx[slot] = g_sx[bN+j];
        sy[slot] = g_sy[bN+j];
        sz[slot] = g_sz[bN+j];
    }
    unsigned sidxp[8];
    {
        const unsigned* su32 = (const unsigned*)(g_sidx + bN);
#pragma unroll
        for (int j = 0; j < 8; j++) sidxp[j] = su32[tid*8 + j];
    }
    __syncthreads();

    const int toff = tid*FPS_PAD;
    // group center + conservative radius
    float gx, gy, gz, gr;
    {
        float sxa = 0.f, sya = 0.f, sza = 0.f;
#pragma unroll
        for (int i = 0; i < 16; i++) { sxa += sx[toff+i]; sya += sy[toff+i]; sza += sz[toff+i]; }
        gx = sxa * 0.0625f; gy = sya * 0.0625f; gz = sza * 0.0625f;
        float md = 0.f;
#pragma unroll
        for (int i = 0; i < 16; i++) {
            float dx = sx[toff+i]-gx, dy = sy[toff+i]-gy, dz = sz[toff+i]-gz;
            md = fmaxf(md, dx*dx + dy*dy + dz*dz);
        }
        gr = sqrtf(md) * 1.00001f + 1e-6f;
    }

    float dist[16];
#pragma unroll
    for (int i = 0; i < 16; i++) dist[i] = __int_as_float(0x7f800000);
    ull bestkey = ((ull)0x7f800000u << 32);   // ub = +inf -> never skip initially

    const int far = far0.v[b];
    const float* xb = xyz + (size_t)b*3*NPTS;
    float cx = xb[far], cy = xb[NPTS+far], cz = xb[2*NPTS+far];

    for (int s = 0; s < NS; s++) {
        if (tid == 0) {
            int q = (b*NS+s)*3;
            newxyz[q+0] = cx; newxyz[q+1] = cy; newxyz[q+2] = cz;
            out_xyz[(size_t)b*3*NS + s]        = cx;
            out_xyz[(size_t)b*3*NS + NS + s]   = cy;
            out_xyz[(size_t)b*3*NS + 2*NS + s] = cz;
        }
        // prune test
        float ddx = cx-gx, ddy = cy-gy, ddz = cz-gz;
        float dcg = ddx*ddx + ddy*ddy + ddz*ddz;
        float ub = __uint_as_float((unsigned)(bestkey >> 32));
        float lb = sqrtf(dcg) * 0.9999995f - gr;
        bool skip = (lb > 0.f) && (lb*lb*0.999999f > ub);
        if (!skip) {
            ull k = 0;
#pragma unroll
            for (int i = 0; i < 16; i++) {
                float dx = sx[toff+i]-cx, dy = sy[toff+i]-cy, dz = sz[toff+i]-cz;
                // match XLA: no fma contraction
                float d = __fadd_rn(__fadd_rn(__fmul_rn(dx,dx),__fmul_rn(dy,dy)),__fmul_rn(dz,dz));
                float dd = fminf(dist[i], d);
                dist[i] = dd;
                unsigned oi = (sidxp[i>>1] >> ((i&1)*16)) & 0xFFFFu;
                k = umax64(k, ((ull)__float_as_uint(dd)<<32) | (0xFFFFFFFFu - oi));
            }
            bestkey = k;
        }
        ull red = bestkey;
#pragma unroll
        for (int off = 16; off; off >>= 1) red = umax64(red, __shfl_down_sync(~0u, red, off));
        if (lane == 0) s_wkey[wid] = red;
        __syncthreads();
        ull ctab = s_wkey[0];
#pragma unroll
        for (int w = 1; w < 32; w++) ctab = umax64(ctab, s_wkey[w]);

        if (bestkey == ctab) {   // unique owner (key carries unique orig index)
            unsigned wi = 0xFFFFFFFFu - (unsigned)ctab;
            int slot = 0;
#pragma unroll
            for (int j = 0; j < 8; j++) {
                unsigned pr = sidxp[j];
                if ((pr & 0xFFFFu) == wi) slot = 2*j;
                if ((pr >> 16)    == wi) slot = 2*j+1;
            }
            s_c[0] = sx[toff+slot]; s_c[1] = sy[toff+slot]; s_c[2] = sz[toff+slot];
        }
        __syncthreads();
        cx = s_c[0]; cy = s_c[1]; cz = s_c[2];
    }
}

// ---------------- kNN radix-select + grouping ----------------
__global__ __launch_bounds__(128,2)
void knn_kernel(const float* __restrict__ xyz, const float* __restrict__ points,
                const float* __restrict__ newxyz, float* __restrict__ X0)
{
    const int blk = blockIdx.x, b = blk >> 10, tid = threadIdx.x;
    const float* xb = xyz + (size_t)b*3*NPTS;
    extern __shared__ char smraw[];
    float* sdist = (float*)smraw;              // 64KB
    int*   hist  = (int*)(smraw + 65536);      // 16KB
    int*   cand  = hist + 4096;                // 8KB
    __shared__ int sel[NK];
    __shared__ int selcnt, candcnt, s_bstar, s_below;
    __shared__ int csum[128];
    __shared__ ull wred[4];
    const float cx = newxyz[blk*3+0], cy = newxyz[blk*3+1], cz = newxyz[blk*3+2];

    for (int i = tid; i < 4096; i += 128) hist[i] = 0;
    if (tid == 0) { selcnt = 0; candcnt = 0; }
    __syncthreads();
    for (int i = 0; i < 128; i++) {
        int n = i*128 + tid;
        float dx = xb[n]-cx, dy = xb[NPTS+n]-cy, dz = xb[2*NPTS+n]-cz;
        float d = dx*dx + dy*dy + dz*dz;
        sdist[n] = d;
        atomicAdd(&hist[__float_as_uint(d)>>20], 1);
    }
    __syncthreads();
    int cs = 0;
    for (int j = 0; j < 32; j++) cs += hist[tid*32+j];
    csum[tid] = cs;
    __syncthreads();
    for (int off = 1; off < 128; off <<= 1) {
        int v = csum[tid];
        int add = (tid >= off) ? csum[tid-off] : 0;
        __syncthreads();
        csum[tid] = v + add;
        __syncthreads();
    }
    int incl = csum[tid], excl = incl - cs;
    if (excl < NK && incl >= NK) {
        int acc = excl, bstar = -1;
        for (int j = 0; j < 32; j++) {
            int h = hist[tid*32+j];
            if (acc + h >= NK) { bstar = tid*32+j; break; }
            acc += h;
        }
        s_bstar = bstar; s_below = acc;
    }
    __syncthreads();
    const int bstar = s_bstar, below = s_below;
    for (int i = 0; i < 128; i++) {
        int n = i*128 + tid;
        int bin = (int)(__float_as_uint(sdist[n])>>20);
        if (bin < bstar)       { int p = atomicAdd(&selcnt,1); sel[p] = n; }
        else if (bin == bstar) { int p = atomicAdd(&candcnt,1); if (p < 2048) cand[p] = n; }
    }
    __syncthreads();
    const int r = NK - below;
    const bool fb = (candcnt > 2048);
    for (int e = 0; e < r; e++) {
        ull best = ~0ull;
        if (!fb) {
            for (int i = tid; i < candcnt; i += 128) {
                int n = cand[i];
                best = umin64(best, ((ull)__float_as_uint(sdist[n])<<32) | (unsigned)n);
            }
        } else {
            for (int i = 0; i < 128; i++) {
                int n = i*128 + tid;
                unsigned u = __float_as_uint(sdist[n]);
                if ((int)(u>>20) == bstar) best = umin64(best, ((ull)u<<32) | (unsigned)n);
            }
        }
#pragma unroll
        for (int off = 16; off; off >>= 1) best = umin64(best, __shfl_down_sync(~0u, best, off));
        if ((tid&31)==0) wred[tid>>5] = best;
        __syncthreads();
        if (tid == 0) {
            best = umin64(umin64(wred[0],wred[1]), umin64(wred[2],wred[3]));
            int n = (int)(unsigned)best;
            sel[below+e] = n;
            sdist[n] = __int_as_float(0x7f800000);
        }
        __syncthreads();
    }
    const size_t mb = (size_t)blk*NK;
    const float* pb = points + (size_t)b*ND*NPTS;
    for (int t = tid; t < NC0*NK; t += 128) {
        int c = t>>5, k = t&31;
        int idx = sel[k];
        float v;
        if (c < 3) {
            float cc = (c==0)?cx:((c==1)?cy:cz);
            v = xb[(size_t)c*NPTS+idx] - cc;
        } else v = pb[(size_t)(c-3)*NPTS+idx];
        X0[(size_t)c*MTOT + mb + k] = v;
    }
}

// ---------------- GEMM 64(o)x128(m) tile ----------------
template <int C>
__global__ __launch_bounds__(256)
void gemm_kernel(const float* __restrict__ X, const float* __restrict__ W,
                 const float* __restrict__ bias, float* __restrict__ Y)
{
    extern __shared__ float smf[];
    float* Ws = smf;           // [C][64]
    float* Xs = smf + C*64;    // [C][128]
    const int m0 = blockIdx.x*128, ob = blockIdx.y*64;
    for (int i = threadIdx.x; i < C*64; i += 256) {
        int o = i&63, c = i>>6;
        Ws[c*64+o] = W[(size_t)(ob+o)*C + c];
    }
    for (int i = threadIdx.x; i < C*128; i += 256) {
        int c = i>>7, j = i&127;
        Xs[c*128+j] = X[(size_t)c*MTOT + m0 + j];
    }
    __syncthreads();
    const int tm = (threadIdx.x&31)*4, to = (threadIdx.x>>5)*8;
    float4 acc[8];
#pragma unroll
    for (int j = 0; j < 8; j++) acc[j] = make_float4(0.f,0.f,0.f,0.f);
#pragma unroll 4
    for (int c = 0; c < C; c++) {
        const float4 xv = *(const float4*)(Xs + c*128 + tm);
        const float4 wa = *(const float4*)(Ws + c*64 + to);
        const float4 wb = *(const float4*)(Ws + c*64 + to + 4);
        const float w[8] = {wa.x,wa.y,wa.z,wa.w,wb.x,wb.y,wb.z,wb.w};
#pragma unroll
        for (int j = 0; j < 8; j++) {
            acc[j].x = fmaf(w[j], xv.x, acc[j].x);
            acc[j].y = fmaf(w[j], xv.y, acc[j].y);
            acc[j].z = fmaf(w[j], xv.z, acc[j].z);
            acc[j].w = fmaf(w[j], xv.w, acc[j].w);
        }
    }
#pragma unroll
    for (int j = 0; j < 8; j++) {
        int row = ob + to + j;
        float bo = bias[row];
        float4 rv = acc[j];
        rv.x += bo; rv.y += bo; rv.z += bo; rv.w += bo;
        *(float4*)(Y + (size_t)row*MTOT + m0 + tm) = rv;
    }
}

// ---------------- BN stats / apply / maxpool ----------------
__global__ void zero_stats_kernel(float* sum, float* ssq)
{
    int i = threadIdx.x;
    if (i < 3*128) { sum[i] = 0.f; ssq[i] = 0.f; }
}

__global__ __launch_bounds__(256)
void stats_kernel(const float* __restrict__ Y, float* __restrict__ sum, float* __restrict__ ssq)
{
    const int o = blockIdx.x >> 5;
    const int chunk = (blockIdx.x & 31) << 13;
    const float* p = Y + (size_t)o*MTOT + chunk;
    float s = 0.f, q = 0.f;
    for (int i = threadIdx.x; i < 8192; i += 256) {
        float v = __ldg(p+i);
        s += v; q += v*v;
    }
#pragma unroll
    for (int off = 16; off; off >>= 1) {
        s += __shfl_down_sync(~0u, s, off);
        q += __shfl_down_sync(~0u, q, off);
    }
    __shared__ float ws[8], wq[8];
    if ((threadIdx.x&31)==0) { ws[threadIdx.x>>5] = s; wq[threadIdx.x>>5] = q; }
    __syncthreads();
    if (threadIdx.x < 8) {
        s = ws[threadIdx.x]; q = wq[threadIdx.x];
#pragma unroll
        for (int off = 4; off; off >>= 1) {
            s += __shfl_down_sync(0xFFu, s, off);
            q += __shfl_down_sync(0xFFu, q, off);
        }
        if (threadIdx.x == 0) { atomicAdd(&sum[o], s); atomicAdd(&ssq[o], q); }
    }
}

__global__ __launch_bounds__(256)
void bn_relu_kernel(float* __restrict__ Y, const float* __restrict__ sum,
                    const float* __restrict__ ssq, const float* __restrict__ gamma,
                    const float* __restrict__ beta)
{
    const int o = blockIdx.x >> 8;
    const int base = (blockIdx.x & 255)*1024 + threadIdx.x*4;
    const float inv = 1.0f/(float)MTOT;
    float mean = sum[o]*inv;
    float var  = ssq[o]*inv - mean*mean;
    float sc = gamma[o]*rsqrtf(var + BN_EPS);
    float sh = beta[o] - sc*mean;
    float4* p = (float4*)(Y + (size_t)o*MTOT + base);
    float4 v = *p;
    v.x = fmaxf(fmaf(sc,v.x,sh),0.f); v.y = fmaxf(fmaf(sc,v.y,sh),0.f);
    v.z = fmaxf(fmaf(sc,v.z,sh),0.f); v.w = fmaxf(fmaf(sc,v.w,sh),0.f);
    *p = v;
}

__global__ __launch_bounds__(256)
void maxpool_kernel(const float* __restrict__ X, float* __restrict__ out)
{
    const int j = blockIdx.x*256 + threadIdx.x;
    const int b = j >> 17, o = (j >> 10) & 127, s = j & 1023;
    const float4* p = (const float4*)(X + (size_t)o*MTOT + ((size_t)(b*NS+s)<<5));
    float m = -__int_as_float(0x7f800000);
#pragma unroll
    for (int i = 0; i < 8; i++) {
        float4 v = p[i];
        m = fmaxf(m, fmaxf(fmaxf(v.x,v.y), fmaxf(v.z,v.w)));
    }
    out[j] = m;
}

// ---------------- host threefry for far0 ----------------
static inline uint32_t rotl32(uint32_t x, int d){ return (x<<d)|(x>>(32-d)); }
static void tf2x32(uint32_t k0, uint32_t k1, uint32_t x0, uint32_t x1,
                   uint32_t* o0, uint32_t* o1)
{
    uint32_t ks[3] = { k0, k1, k0^k1^0x1BD11BDAu };
    x0 += ks[0]; x1 += ks[1];
    static const int R[2][4] = { {13,15,26,6}, {17,29,16,24} };
    for (int g = 0; g < 5; g++) {
        const int* r = R[g&1];
        for (int i = 0; i < 4; i++) { x0 += x1; x1 = rotl32(x1, r[i]); x1 ^= x0; }
        x0 += ks[(g+1)%3];
        x1 += ks[(g+2)%3] + (uint32_t)(g+1);
    }
    *o0 = x0; *o1 = x1;
}
static void compute_far0(int* far)
{
    // jax.random.randint(key(42),(8,),0,16384), threefry_partitionable:
    // k2 = block(key,(0,1)); bits[i] = o0^o1 of block(k2,(0,i)); far = bits & 16383
    uint32_t ka, kb;
    tf2x32(0u, 42u, 0u, 1u, &ka, &kb);
    for (int i = 0; i < NB; i++) {
        uint32_t o0, o1;
        tf2x32(ka, kb, 0u, (uint32_t)i, &o0, &o1);
        far[i] = (int)((o0 ^ o1) & (NPTS - 1));
    }
}

extern "C" void kernel_launch(void* const* d_in, const int* in_sizes, int n_in,
                              void* d_out, int out_size)
{
    const float* xyz    = (const float*)d_in[0];
    const float* points = (const float*)d_in[1];
    const float* w0 = (const float*)d_in[2];
    const float* b0 = (const float*)d_in[3];
    const float* g0 = (const float*)d_in[4];
    const float* be0= (const float*)d_in[5];
    const float* w1 = (const float*)d_in[6];
    const float* b1 = (const float*)d_in[7];
    const float* g1 = (const float*)d_in[8];
    const float* be1= (const float*)d_in[9];
    const float* w2 = (const float*)d_in[10];
    const float* b2 = (const float*)d_in[11];
    const float* g2 = (const float*)d_in[12];
    const float* be2= (const float*)d_in[13];
    float* out = (float*)d_out;

    Far0 f; compute_far0(f.v);

    float *X0,*A,*Bf,*Y3,*nxyz,*sum,*ssq;
    cudaGetSymbolAddress((void**)&X0, g_X0);
    cudaGetSymbolAddress((void**)&A,  g_A);
    cudaGetSymbolAddress((void**)&Bf, g_Bf);
    cudaGetSymbolAddress((void**)&Y3, g_Y3);
    cudaGetSymbolAddress((void**)&nxyz, g_newxyz);
    cudaGetSymbolAddress((void**)&sum, g_sum);
    cudaGetSymbolAddress((void**)&ssq, g_ssq);

    const int FPS_SMEM = 3 * 1024 * FPS_PAD * 4;   // 208896
    const int KNN_SMEM = 65536 + 16384 + 8192;
    const int G67_SMEM = (NC0*64 + NC0*128)*4;
    const int G64_SMEM = (64*64 + 64*128)*4;
    cudaFuncSetAttribute(fps_kernel, cudaFuncAttributeMaxDynamicSharedMemorySize, FPS_SMEM);
    cudaFuncSetAttribute(knn_kernel, cudaFuncAttributeMaxDynamicSharedMemorySize, KNN_SMEM);
    cudaFuncSetAttribute(gemm_kernel<NC0>, cudaFuncAttributeMaxDynamicSharedMemorySize, G67_SMEM);
    cudaFuncSetAttribute(gemm_kernel<64>,  cudaFuncAttributeMaxDynamicSharedMemorySize, G64_SMEM);

    sort_kernel<<<NB, 1024>>>(xyz);
    fps_kernel<<<NB, 1024, FPS_SMEM>>>(xyz, nxyz, out, f);
    knn_kernel<<<NB*NS, 128, KNN_SMEM>>>(xyz, points, nxyz, X0);

    zero_stats_kernel<<<1, 512>>>(sum, ssq);

    gemm_kernel<NC0><<<dim3(MTOT/128,1), 256, G67_SMEM>>>(X0, w0, b0, A);
    stats_kernel<<<64*32, 256>>>(A, sum+0, ssq+0);
    bn_relu_kernel<<<64*256, 256>>>(A, sum+0, ssq+0, g0, be0);

    gemm_kernel<64><<<dim3(MTOT/128,1), 256, G64_SMEM>>>(A, w1, b1, Bf);
    stats_kernel<<<64*32, 256>>>(Bf, sum+64, ssq+64);
    bn_relu_kernel<<<64*256, 256>>>(Bf, sum+64, ssq+64, g1, be1);

    gemm_kernel<64><<<dim3(MTOT/128,2), 256, G64_SMEM>>>(Bf, w2, b2, Y3);
    stats_kernel<<<128*32, 256>>>(Y3, sum+128, ssq+128);
    bn_relu_kernel<<<128*256, 256>>>(Y3, sum+128, ssq+128, g2, be2);

    maxpool_kernel<<<(NB*128*NS)/256, 256>>>(Y3, out + NB*3*NS);
}

// round 15
// speedup vs baseline: 1.4015x; 1.2873x over previous
#include <cuda_runtime.h>
#include <cstdint>

#define NB 8
#define NPTS 16384
#define NS 1024
#define NK 32
#define ND 64
#define NC0 67
#define MTOT (NB*NS*NK)
#define BN_EPS 1e-5f
typedef unsigned long long ull;

__device__ float g_X0[(size_t)NC0*MTOT];
__device__ float g_A [(size_t)64 *MTOT];
__device__ float g_Bf[(size_t)64 *MTOT];
__device__ float g_Y3[(size_t)128*MTOT];
__device__ float g_newxyz[NB*NS*3];
__device__ float g_sum[3*128];
__device__ float g_ssq[3*128];

struct Far0 { int v[NB]; };
__device__ __forceinline__ ull umax64(ull a, ull b){ return a>b?a:b; }
__device__ __forceinline__ ull umin64(ull a, ull b){ return a<b?a:b; }

// ---------------- FPS: one block/batch, instruction-diet reduce ----------------
__global__ __launch_bounds__(1024,1)
void fps_kernel(const float* __restrict__ xyz,
                float* __restrict__ newxyz, float* __restrict__ out_xyz, Far0 far0)
{
    const int b = blockIdx.x, tid = threadIdx.x;
    const int wid = tid >> 5, lane = tid & 31;
    const float* xb = xyz + (size_t)b*3*NPTS;
    extern __shared__ char smraw[];
    float2* sxy = (float2*)smraw;                    // 16384 * 8B
    float*  sz  = (float*)(smraw + (size_t)NPTS*8);  // 16384 * 4B
    __shared__ ull s_wkey[2][32];                    // parity double-buffered

    for (int i = tid; i < NPTS; i += 1024) {
        sxy[i] = make_float2(xb[i], xb[NPTS+i]);
        sz[i]  = xb[2*NPTS+i];
    }
    __syncthreads();

    float dist[16];
#pragma unroll
    for (int i = 0; i < 16; i++) dist[i] = __int_as_float(0x7f800000);

    const int far = far0.v[b];
    float cx = xb[far], cy = xb[NPTS+far], cz = xb[2*NPTS+far];

    for (int s = 0; s < NS; s++) {
        const int p = s & 1;
        if (tid == 0) {
            int q = (b*NS+s)*3;
            newxyz[q+0] = cx; newxyz[q+1] = cy; newxyz[q+2] = cz;
            out_xyz[(size_t)b*3*NS + s]        = cx;
            out_xyz[(size_t)b*3*NS + NS + s]   = cy;
            out_xyz[(size_t)b*3*NS + 2*NS + s] = cz;
        }
        // distance update + float max (no per-point 64-bit keys)
        float m = 0.f;
#pragma unroll
        for (int i = 0; i < 16; i++) {
            int n = tid + i*1024;
            float2 pt = sxy[n]; float ptz = sz[n];
            float dx = pt.x-cx, dy = pt.y-cy, dz = ptz-cz;
            // match XLA: no fma contraction
            float d = __fadd_rn(__fadd_rn(__fmul_rn(dx,dx),__fmul_rn(dy,dy)),__fmul_rn(dz,dz));
            float dd = fminf(dist[i], d);
            dist[i] = dd;
            m = fmaxf(m, dd);
        }
        // lowest index among this thread's maxima (n increases with i)
        unsigned idx = 0xFFFFFFFFu;
#pragma unroll
        for (int i = 0; i < 16; i++)
            if (dist[i] == m) idx = idx < (unsigned)(tid + i*1024) ? idx : (unsigned)(tid + i*1024);
        ull key = ((ull)__float_as_uint(m) << 32) | (0xFFFFFFFFu - idx);
        // warp reduce (lane0 gets warp winner)
#pragma unroll
        for (int off = 16; off; off >>= 1) key = umax64(key, __shfl_down_sync(~0u, key, off));
        if (lane == 0) s_wkey[p][wid] = key;
        __syncthreads();
        // every warp: read 32 warp-winners, xor-shfl so ALL lanes get block winner
        ull k2 = s_wkey[p][lane];
#pragma unroll
        for (int off = 16; off; off >>= 1) k2 = umax64(k2, __shfl_xor_sync(~0u, k2, off));
        unsigned win = 0xFFFFFFFFu - (unsigned)k2;
        float2 wxy = sxy[win];            // broadcast LDS (same address)
        cx = wxy.x; cy = wxy.y; cz = sz[win];
        // no second barrier: s_wkey parity double-buffered
    }
}

// ---------------- kNN radix-select + grouping ----------------
__global__ __launch_bounds__(128,2)
void knn_kernel(const float* __restrict__ xyz, const float* __restrict__ points,
                const float* __restrict__ newxyz, float* __restrict__ X0)
{
    const int blk = blockIdx.x, b = blk >> 10, tid = threadIdx.x;
    const float* xb = xyz + (size_t)b*3*NPTS;
    extern __shared__ char smraw[];
    float* sdist = (float*)smraw;              // 64KB
    int*   hist  = (int*)(smraw + 65536);      // 16KB
    int*   cand  = hist + 4096;                // 8KB
    __shared__ int sel[NK];
    __shared__ int selcnt, candcnt, s_bstar, s_below;
    __shared__ int csum[128];
    __shared__ ull wred[4];
    const float cx = newxyz[blk*3+0], cy = newxyz[blk*3+1], cz = newxyz[blk*3+2];

    for (int i = tid; i < 4096; i += 128) hist[i] = 0;
    if (tid == 0) { selcnt = 0; candcnt = 0; }
    __syncthreads();
    for (int i = 0; i < 128; i++) {
        int n = i*128 + tid;
        float dx = xb[n]-cx, dy = xb[NPTS+n]-cy, dz = xb[2*NPTS+n]-cz;
        float d = dx*dx + dy*dy + dz*dz;
        sdist[n] = d;
        atomicAdd(&hist[__float_as_uint(d)>>20], 1);
    }
    __syncthreads();
    int cs = 0;
    for (int j = 0; j < 32; j++) cs += hist[tid*32+j];
    csum[tid] = cs;
    __syncthreads();
    for (int off = 1; off < 128; off <<= 1) {
        int v = csum[tid];
        int add = (tid >= off) ? csum[tid-off] : 0;
        __syncthreads();
        csum[tid] = v + add;
        __syncthreads();
    }
    int incl = csum[tid], excl = incl - cs;
    if (excl < NK && incl >= NK) {
        int acc = excl, bstar = -1;
        for (int j = 0; j < 32; j++) {
            int h = hist[tid*32+j];
            if (acc + h >= NK) { bstar = tid*32+j; break; }
            acc += h;
        }
        s_bstar = bstar; s_below = acc;
    }
    __syncthreads();
    const int bstar = s_bstar, below = s_below;
    for (int i = 0; i < 128; i++) {
        int n = i*128 + tid;
        int bin = (int)(__float_as_uint(sdist[n])>>20);
        if (bin < bstar)       { int p = atomicAdd(&selcnt,1); sel[p] = n; }
        else if (bin == bstar) { int p = atomicAdd(&candcnt,1); if (p < 2048) cand[p] = n; }
    }
    __syncthreads();
    const int r = NK - below;
    const bool fb = (candcnt > 2048);
    for (int e = 0; e < r; e++) {
        ull best = ~0ull;
        if (!fb) {
            for (int i = tid; i < candcnt; i += 128) {
                int n = cand[i];
                best = umin64(best, ((ull)__float_as_uint(sdist[n])<<32) | (unsigned)n);
            }
        } else {
            for (int i = 0; i < 128; i++) {
                int n = i*128 + tid;
                unsigned u = __float_as_uint(sdist[n]);
                if ((int)(u>>20) == bstar) best = umin64(best, ((ull)u<<32) | (unsigned)n);
            }
        }
#pragma unroll
        for (int off = 16; off; off >>= 1) best = umin64(best, __shfl_down_sync(~0u, best, off));
        if ((tid&31)==0) wred[tid>>5] = best;
        __syncthreads();
        if (tid == 0) {
            best = umin64(umin64(wred[0],wred[1]), umin64(wred[2],wred[3]));
            int n = (int)(unsigned)best;
            sel[below+e] = n;
            sdist[n] = __int_as_float(0x7f800000);
        }
        __syncthreads();
    }
    const size_t mb = (size_t)blk*NK;
    const float* pb = points + (size_t)b*ND*NPTS;
    for (int t = tid; t < NC0*NK; t += 128) {
        int c = t>>5, k = t&31;
        int idx = sel[k];
        float v;
        if (c < 3) {
            float cc = (c==0)?cx:((c==1)?cy:cz);
            v = xb[(size_t)c*NPTS+idx] - cc;
        } else v = pb[(size_t)(c-3)*NPTS+idx];
        X0[(size_t)c*MTOT + mb + k] = v;
    }
}

// ---------------- GEMM 64(o)x128(m) tile ----------------
template <int C>
__global__ __launch_bounds__(256)
void gemm_kernel(const float* __restrict__ X, const float* __restrict__ W,
                 const float* __restrict__ bias, float* __restrict__ Y)
{
    extern __shared__ float smf[];
    float* Ws = smf;           // [C][64]
    float* Xs = smf + C*64;    // [C][128]
    const int m0 = blockIdx.x*128, ob = blockIdx.y*64;
    for (int i = threadIdx.x; i < C*64; i += 256) {
        int o = i&63, c = i>>6;
        Ws[c*64+o] = W[(size_t)(ob+o)*C + c];
    }
    for (int i = threadIdx.x; i < C*128; i += 256) {
        int c = i>>7, j = i&127;
        Xs[c*128+j] = X[(size_t)c*MTOT + m0 + j];
    }
    __syncthreads();
    const int tm = (threadIdx.x&31)*4, to = (threadIdx.x>>5)*8;
    float4 acc[8];
#pragma unroll
    for (int j = 0; j < 8; j++) acc[j] = make_float4(0.f,0.f,0.f,0.f);
#pragma unroll 4
    for (int c = 0; c < C; c++) {
        const float4 xv = *(const float4*)(Xs + c*128 + tm);
        const float4 wa = *(const float4*)(Ws + c*64 + to);
        const float4 wb = *(const float4*)(Ws + c*64 + to + 4);
        const float w[8] = {wa.x,wa.y,wa.z,wa.w,wb.x,wb.y,wb.z,wb.w};
#pragma unroll
        for (int j = 0; j < 8; j++) {
            acc[j].x = fmaf(w[j], xv.x, acc[j].x);
            acc[j].y = fmaf(w[j], xv.y, acc[j].y);
            acc[j].z = fmaf(w[j], xv.z, acc[j].z);
            acc[j].w = fmaf(w[j], xv.w, acc[j].w);
        }
    }
#pragma unroll
    for (int j = 0; j < 8; j++) {
        int row = ob + to + j;
        float bo = bias[row];
        float4 rv = acc[j];
        rv.x += bo; rv.y += bo; rv.z += bo; rv.w += bo;
        *(float4*)(Y + (size_t)row*MTOT + m0 + tm) = rv;
    }
}

// ---------------- BN stats / apply / maxpool ----------------
__global__ void zero_stats_kernel(float* sum, float* ssq)
{
    int i = threadIdx.x;
    if (i < 3*128) { sum[i] = 0.f; ssq[i] = 0.f; }
}

__global__ __launch_bounds__(256)
void stats_kernel(const float* __restrict__ Y, float* __restrict__ sum, float* __restrict__ ssq)
{
    const int o = blockIdx.x >> 5;
    const int chunk = (blockIdx.x & 31) << 13;
    const float* p = Y + (size_t)o*MTOT + chunk;
    float s = 0.f, q = 0.f;
    for (int i = threadIdx.x; i < 8192; i += 256) {
        float v = __ldg(p+i);
        s += v; q += v*v;
    }
#pragma unroll
    for (int off = 16; off; off >>= 1) {
        s += __shfl_down_sync(~0u, s, off);
        q += __shfl_down_sync(~0u, q, off);
    }
    __shared__ float ws[8], wq[8];
    if ((threadIdx.x&31)==0) { ws[threadIdx.x>>5] = s; wq[threadIdx.x>>5] = q; }
    __syncthreads();
    if (threadIdx.x < 8) {
        s = ws[threadIdx.x]; q = wq[threadIdx.x];
#pragma unroll
        for (int off = 4; off; off >>= 1) {
            s += __shfl_down_sync(0xFFu, s, off);
            q += __shfl_down_sync(0xFFu, q, off);
        }
        if (threadIdx.x == 0) { atomicAdd(&sum[o], s); atomicAdd(&ssq[o], q); }
    }
}

__global__ __launch_bounds__(256)
void bn_relu_kernel(float* __restrict__ Y, const float* __restrict__ sum,
                    const float* __restrict__ ssq, const float* __restrict__ gamma,
                    const float* __restrict__ beta)
{
    const int o = blockIdx.x >> 8;
    const int base = (blockIdx.x & 255)*1024 + threadIdx.x*4;
    const float inv = 1.0f/(float)MTOT;
    float mean = sum[o]*inv;
    float var  = ssq[o]*inv - mean*mean;
    float sc = gamma[o]*rsqrtf(var + BN_EPS);
    float sh = beta[o] - sc*mean;
    float4* p = (float4*)(Y + (size_t)o*MTOT + base);
    float4 v = *p;
    v.x = fmaxf(fmaf(sc,v.x,sh),0.f); v.y = fmaxf(fmaf(sc,v.y,sh),0.f);
    v.z = fmaxf(fmaf(sc,v.z,sh),0.f); v.w = fmaxf(fmaf(sc,v.w,sh),0.f);
    *p = v;
}

__global__ __launch_bounds__(256)
void maxpool_kernel(const float* __restrict__ X, float* __restrict__ out)
{
    const int j = blockIdx.x*256 + threadIdx.x;
    const int b = j >> 17, o = (j >> 10) & 127, s = j & 1023;
    const float4* p = (const float4*)(X + (size_t)o*MTOT + ((size_t)(b*NS+s)<<5));
    float m = -__int_as_float(0x7f800000);
#pragma unroll
    for (int i = 0; i < 8; i++) {
        float4 v = p[i];
        m = fmaxf(m, fmaxf(fmaxf(v.x,v.y), fmaxf(v.z,v.w)));
    }
    out[j] = m;
}

// ---------------- host threefry for far0 ----------------
static inline uint32_t rotl32(uint32_t x, int d){ return (x<<d)|(x>>(32-d)); }
static void tf2x32(uint32_t k0, uint32_t k1, uint32_t x0, uint32_t x1,
                   uint32_t* o0, uint32_t* o1)
{
    uint32_t ks[3] = { k0, k1, k0^k1^0x1BD11BDAu };
    x0 += ks[0]; x1 += ks[1];
    static const int R[2][4] = { {13,15,26,6}, {17,29,16,24} };
    for (int g = 0; g < 5; g++) {
        const int* r = R[g&1];
        for (int i = 0; i < 4; i++) { x0 += x1; x1 = rotl32(x1, r[i]); x1 ^= x0; }
        x0 += ks[(g+1)%3];
        x1 += ks[(g+2)%3] + (uint32_t)(g+1);
    }
    *o0 = x0; *o1 = x1;
}
static void compute_far0(int* far)
{
    // jax.random.randint(key(42),(8,),0,16384), threefry_partitionable:
    // k2 = block(key,(0,1)); bits[i] = o0^o1 of block(k2,(0,i)); far = bits & 16383
    uint32_t ka, kb;
    tf2x32(0u, 42u, 0u, 1u, &ka, &kb);
    for (int i = 0; i < NB; i++) {
        uint32_t o0, o1;
        tf2x32(ka, kb, 0u, (uint32_t)i, &o0, &o1);
        far[i] = (int)((o0 ^ o1) & (NPTS - 1));
    }
}

extern "C" void kernel_launch(void* const* d_in, const int* in_sizes, int n_in,
                              void* d_out, int out_size)
{
    const float* xyz    = (const float*)d_in[0];
    const float* points = (const float*)d_in[1];
    const float* w0 = (const float*)d_in[2];
    const float* b0 = (const float*)d_in[3];
    const float* g0 = (const float*)d_in[4];
    const float* be0= (const float*)d_in[5];
    const float* w1 = (const float*)d_in[6];
    const float* b1 = (const float*)d_in[7];
    const float* g1 = (const float*)d_in[8];
    const float* be1= (const float*)d_in[9];
    const float* w2 = (const float*)d_in[10];
    const float* b2 = (const float*)d_in[11];
    const float* g2 = (const float*)d_in[12];
    const float* be2= (const float*)d_in[13];
    float* out = (float*)d_out;

    Far0 f; compute_far0(f.v);

    float *X0,*A,*Bf,*Y3,*nxyz,*sum,*ssq;
    cudaGetSymbolAddress((void**)&X0, g_X0);
    cudaGetSymbolAddress((void**)&A,  g_A);
    cudaGetSymbolAddress((void**)&Bf, g_Bf);
    cudaGetSymbolAddress((void**)&Y3, g_Y3);
    cudaGetSymbolAddress((void**)&nxyz, g_newxyz);
    cudaGetSymbolAddress((void**)&sum, g_sum);
    cudaGetSymbolAddress((void**)&ssq, g_ssq);

    const int FPS_SMEM = NPTS*12;                  // 196608
    const int KNN_SMEM = 65536 + 16384 + 8192;
    const int G67_SMEM = (NC0*64 + NC0*128)*4;
    const int G64_SMEM = (64*64 + 64*128)*4;
    cudaFuncSetAttribute(fps_kernel, cudaFuncAttributeMaxDynamicSharedMemorySize, FPS_SMEM);
    cudaFuncSetAttribute(knn_kernel, cudaFuncAttributeMaxDynamicSharedMemorySize, KNN_SMEM);
    cudaFuncSetAttribute(gemm_kernel<NC0>, cudaFuncAttributeMaxDynamicSharedMemorySize, G67_SMEM);
    cudaFuncSetAttribute(gemm_kernel<64>,  cudaFuncAttributeMaxDynamicSharedMemorySize, G64_SMEM);

    fps_kernel<<<NB, 1024, FPS_SMEM>>>(xyz, nxyz, out, f);
    knn_kernel<<<NB*NS, 128, KNN_SMEM>>>(xyz, points, nxyz, X0);

    zero_stats_kernel<<<1, 512>>>(sum, ssq);

    gemm_kernel<NC0><<<dim3(MTOT/128,1), 256, G67_SMEM>>>(X0, w0, b0, A);
    stats_kernel<<<64*32, 256>>>(A, sum+0, ssq+0);
    bn_relu_kernel<<<64*256, 256>>>(A, sum+0, ssq+0, g0, be0);

    gemm_kernel<64><<<dim3(MTOT/128,1), 256, G64_SMEM>>>(A, w1, b1, Bf);
    stats_kernel<<<64*32, 256>>>(Bf, sum+64, ssq+64);
    bn_relu_kernel<<<64*256, 256>>>(Bf, sum+64, ssq+64, g1, be1);

    gemm_kernel<64><<<dim3(MTOT/128,2), 256, G64_SMEM>>>(Bf, w2, b2, Y3);
    stats_kernel<<<128*32, 256>>>(Y3, sum+128, ssq+128);
    bn_relu_kernel<<<128*256, 256>>>(Y3, sum+128, ssq+128, g2, be2);

    maxpool_kernel<<<(NB*128*NS)/256, 256>>>(Y3, out + NB*3*NS);
}

// round 16
// speedup vs baseline: 1.4017x; 1.0001x over previous
#include <cuda_runtime.h>
#include <cstdint>

#define NB 8
#define NPTS 16384
#define NS 1024
#define NK 32
#define ND 64
#define NC0 67
#define MTOT (NB*NS*NK)
#define BN_EPS 1e-5f
typedef unsigned long long ull;

__device__ float g_X0[(size_t)NC0*MTOT];
__device__ float g_A [(size_t)64 *MTOT];
__device__ float g_Bf[(size_t)64 *MTOT];
__device__ float g_Y3[(size_t)128*MTOT];
__device__ float g_newxyz[NB*NS*3];
__device__ float g_sum[3*128];
__device__ float g_ssq[3*128];

struct Far0 { int v[NB]; };
__device__ __forceinline__ ull umax64(ull a, ull b){ return a>b?a:b; }
__device__ __forceinline__ ull umin64(ull a, ull b){ return a<b?a:b; }

__device__ __forceinline__ uint32_t mapa_sh(uint32_t a, uint32_t r){
    uint32_t d; asm("mapa.shared::cluster.u32 %0, %1, %2;" : "=r"(d) : "r"(a), "r"(r));
    return d;
}
__device__ __forceinline__ void st_cl64(uint32_t a, ull v){
    asm volatile("st.shared::cluster.u64 [%0], %1;" :: "r"(a), "l"(v) : "memory");
}
__device__ __forceinline__ void st_cl32(uint32_t a, float v){
    asm volatile("st.shared::cluster.f32 [%0], %1;" :: "r"(a), "f"(v) : "memory");
}
__device__ __forceinline__ void cluster_sync_(){
    asm volatile("barrier.cluster.arrive.aligned;" ::: "memory");
    asm volatile("barrier.cluster.wait.aligned;" ::: "memory");
}

// ---------------- FPS: cluster of 2 CTAs per batch ----------------
// Each CTA owns 8192 points (96KB SMEM -> half the crossbar traffic of the
// single-CTA version). One cluster barrier per iteration; winner slot
// (key + coords) double-buffered by parity.
#define FPS_HALF (NPTS/2)     // 8192
#define FPS_PPT  8            // points per thread

__global__ __launch_bounds__(1024,1) __cluster_dims__(2,1,1)
void fps_kernel(const float* __restrict__ xyz,
                float* __restrict__ newxyz, float* __restrict__ out_xyz, Far0 far0)
{
    const unsigned rank = (unsigned)(blockIdx.x & 1);
    const int b = blockIdx.x >> 1;
    const int tid = threadIdx.x;
    const int wid = tid >> 5, lane = tid & 31;
    const float* xb = xyz + (size_t)b*3*NPTS;
    const unsigned gbase = rank*FPS_HALF;

    extern __shared__ char smraw[];
    float2* sxy = (float2*)smraw;                         // 8192*8B
    float*  sz  = (float*)(smraw + (size_t)FPS_HALF*8);   // 8192*4B
    __shared__ ull s_wkey[2][32];
    __shared__ ull s_slotk[2][2];
    __shared__ float s_slotx[2][2], s_sloty[2][2], s_slotz[2][2];

    for (int i = tid; i < FPS_HALF; i += 1024) {
        unsigned n = gbase + i;
        sxy[i] = make_float2(xb[n], xb[NPTS+n]);
        sz[i]  = xb[2*NPTS+n];
    }

    float dist[FPS_PPT];
#pragma unroll
    for (int i = 0; i < FPS_PPT; i++) dist[i] = __int_as_float(0x7f800000);

    const int far = far0.v[b];
    float cx = xb[far], cy = xb[NPTS+far], cz = xb[2*NPTS+far];
    __syncthreads();          // SMEM tiles ready (cluster sync below covers peer)
    cluster_sync_();          // both CTAs' slots/tiles valid before first use

    for (int s = 0; s < NS; s++) {
        const int p = s & 1;
        if (rank == 0 && tid == 0) {
            int q = (b*NS+s)*3;
            newxyz[q+0] = cx; newxyz[q+1] = cy; newxyz[q+2] = cz;
            out_xyz[(size_t)b*3*NS + s]        = cx;
            out_xyz[(size_t)b*3*NS + NS + s]   = cy;
            out_xyz[(size_t)b*3*NS + 2*NS + s] = cz;
        }
        float m = 0.f;
#pragma unroll
        for (int i = 0; i < FPS_PPT; i++) {
            int l = tid + i*1024;
            float2 pt = sxy[l]; float ptz = sz[l];
            float dx = pt.x-cx, dy = pt.y-cy, dz = ptz-cz;
            // match XLA: no fma contraction
            float d = __fadd_rn(__fadd_rn(__fmul_rn(dx,dx),__fmul_rn(dy,dy)),__fmul_rn(dz,dz));
            float dd = fminf(dist[i], d);
            dist[i] = dd;
            m = fmaxf(m, dd);
        }
        unsigned idx = 0xFFFFFFFFu;   // lowest global index among this thread's maxima
#pragma unroll
        for (int i = 0; i < FPS_PPT; i++) {
            unsigned n = gbase + (unsigned)(tid + i*1024);
            if (dist[i] == m) idx = idx < n ? idx : n;
        }
        ull key = ((ull)__float_as_uint(m) << 32) | (0xFFFFFFFFu - idx);
#pragma unroll
        for (int off = 16; off; off >>= 1) key = umax64(key, __shfl_down_sync(~0u, key, off));
        if (lane == 0) s_wkey[p][wid] = key;
        __syncthreads();
        ull k2 = s_wkey[p][lane];
#pragma unroll
        for (int off = 16; off; off >>= 1) k2 = umax64(k2, __shfl_xor_sync(~0u, k2, off));
        // CTA winner coords (local by construction), broadcast LDS
        unsigned winl = (0xFFFFFFFFu - (unsigned)k2) - gbase;
        float2 wxy = sxy[winl]; float wz = sz[winl];
        if (tid == 0) {
            s_slotk[p][rank] = k2;
            s_slotx[p][rank] = wxy.x; s_sloty[p][rank] = wxy.y; s_slotz[p][rank] = wz;
            uint32_t ak = (uint32_t)__cvta_generic_to_shared(&s_slotk[p][rank]);
            uint32_t ax = (uint32_t)__cvta_generic_to_shared(&s_slotx[p][rank]);
            uint32_t ay = (uint32_t)__cvta_generic_to_shared(&s_sloty[p][rank]);
            uint32_t az = (uint32_t)__cvta_generic_to_shared(&s_slotz[p][rank]);
            unsigned peer = rank ^ 1u;
            st_cl64(mapa_sh(ak, peer), k2);
            st_cl32(mapa_sh(ax, peer), wxy.x);
            st_cl32(mapa_sh(ay, peer), wxy.y);
            st_cl32(mapa_sh(az, peer), wz);
        }
        cluster_sync_();
        ull k0 = s_slotk[p][0], k1 = s_slotk[p][1];
        int j = (k1 > k0) ? 1 : 0;
        cx = s_slotx[p][j]; cy = s_sloty[p][j]; cz = s_slotz[p][j];
    }
}

// ---------------- kNN radix-select + grouping ----------------
__global__ __launch_bounds__(128,2)
void knn_kernel(const float* __restrict__ xyz, const float* __restrict__ points,
                const float* __restrict__ newxyz, float* __restrict__ X0)
{
    const int blk = blockIdx.x, b = blk >> 10, tid = threadIdx.x;
    const float* xb = xyz + (size_t)b*3*NPTS;
    extern __shared__ char smraw[];
    float* sdist = (float*)smraw;              // 64KB
    int*   hist  = (int*)(smraw + 65536);      // 16KB
    int*   cand  = hist + 4096;                // 8KB
    __shared__ int sel[NK];
    __shared__ int selcnt, candcnt, s_bstar, s_below;
    __shared__ int csum[128];
    __shared__ ull wred[4];
    const float cx = newxyz[blk*3+0], cy = newxyz[blk*3+1], cz = newxyz[blk*3+2];

    for (int i = tid; i < 4096; i += 128) hist[i] = 0;
    if (tid == 0) { selcnt = 0; candcnt = 0; }
    __syncthreads();
    for (int i = 0; i < 128; i++) {
        int n = i*128 + tid;
        float dx = xb[n]-cx, dy = xb[NPTS+n]-cy, dz = xb[2*NPTS+n]-cz;
        float d = dx*dx + dy*dy + dz*dz;
        sdist[n] = d;
        atomicAdd(&hist[__float_as_uint(d)>>20], 1);
    }
    __syncthreads();
    int cs = 0;
    for (int j = 0; j < 32; j++) cs += hist[tid*32+j];
    csum[tid] = cs;
    __syncthreads();
    for (int off = 1; off < 128; off <<= 1) {
        int v = csum[tid];
        int add = (tid >= off) ? csum[tid-off] : 0;
        __syncthreads();
        csum[tid] = v + add;
        __syncthreads();
    }
    int incl = csum[tid], excl = incl - cs;
    if (excl < NK && incl >= NK) {
        int acc = excl, bstar = -1;
        for (int j = 0; j < 32; j++) {
            int h = hist[tid*32+j];
            if (acc + h >= NK) { bstar = tid*32+j; break; }
            acc += h;
        }
        s_bstar = bstar; s_below = acc;
    }
    __syncthreads();
    const int bstar = s_bstar, below = s_below;
    for (int i = 0; i < 128; i++) {
        int n = i*128 + tid;
        int bin = (int)(__float_as_uint(sdist[n])>>20);
        if (bin < bstar)       { int p = atomicAdd(&selcnt,1); sel[p] = n; }
        else if (bin == bstar) { int p = atomicAdd(&candcnt,1); if (p < 2048) cand[p] = n; }
    }
    __syncthreads();
    const int r = NK - below;
    const bool fb = (candcnt > 2048);
    for (int e = 0; e < r; e++) {
        ull best = ~0ull;
        if (!fb) {
            for (int i = tid; i < candcnt; i += 128) {
                int n = cand[i];
                best = umin64(best, ((ull)__float_as_uint(sdist[n])<<32) | (unsigned)n);
            }
        } else {
            for (int i = 0; i < 128; i++) {
                int n = i*128 + tid;
                unsigned u = __float_as_uint(sdist[n]);
                if ((int)(u>>20) == bstar) best = umin64(best, ((ull)u<<32) | (unsigned)n);
            }
        }
#pragma unroll
        for (int off = 16; off; off >>= 1) best = umin64(best, __shfl_down_sync(~0u, best, off));
        if ((tid&31)==0) wred[tid>>5] = best;
        __syncthreads();
        if (tid == 0) {
            best = umin64(umin64(wred[0],wred[1]), umin64(wred[2],wred[3]));
            int n = (int)(unsigned)best;
            sel[below+e] = n;
            sdist[n] = __int_as_float(0x7f800000);
        }
        __syncthreads();
    }
    const size_t mb = (size_t)blk*NK;
    const float* pb = points + (size_t)b*ND*NPTS;
    for (int t = tid; t < NC0*NK; t += 128) {
        int c = t>>5, k = t&31;
        int idx = sel[k];
        float v;
        if (c < 3) {
            float cc = (c==0)?cx:((c==1)?cy:cz);
            v = xb[(size_t)c*NPTS+idx] - cc;
        } else v = pb[(size_t)(c-3)*NPTS+idx];
        X0[(size_t)c*MTOT + mb + k] = v;
    }
}

// ---------------- GEMM 64(o)x128(m) tile ----------------
template <int C>
__global__ __launch_bounds__(256)
void gemm_kernel(const float* __restrict__ X, const float* __restrict__ W,
                 const float* __restrict__ bias, float* __restrict__ Y)
{
    extern __shared__ float smf[];
    float* Ws = smf;           // [C][64]
    float* Xs = smf + C*64;    // [C][128]
    const int m0 = blockIdx.x*128, ob = blockIdx.y*64;
    for (int i = threadIdx.x; i < C*64; i += 256) {
        int o = i&63, c = i>>6;
        Ws[c*64+o] = W[(size_t)(ob+o)*C + c];
    }
    for (int i = threadIdx.x; i < C*128; i += 256) {
        int c = i>>7, j = i&127;
        Xs[c*128+j] = X[(size_t)c*MTOT + m0 + j];
    }
    __syncthreads();
    const int tm = (threadIdx.x&31)*4, to = (threadIdx.x>>5)*8;
    float4 acc[8];
#pragma unroll
    for (int j = 0; j < 8; j++) acc[j] = make_float4(0.f,0.f,0.f,0.f);
#pragma unroll 4
    for (int c = 0; c < C; c++) {
        const float4 xv = *(const float4*)(Xs + c*128 + tm);
        const float4 wa = *(const float4*)(Ws + c*64 + to);
        const float4 wb = *(const float4*)(Ws + c*64 + to + 4);
        const float w[8] = {wa.x,wa.y,wa.z,wa.w,wb.x,wb.y,wb.z,wb.w};
#pragma unroll
        for (int j = 0; j < 8; j++) {
            acc[j].x = fmaf(w[j], xv.x, acc[j].x);
            acc[j].y = fmaf(w[j], xv.y, acc[j].y);
            acc[j].z = fmaf(w[j], xv.z, acc[j].z);
            acc[j].w = fmaf(w[j], xv.w, acc[j].w);
        }
    }
#pragma unroll
    for (int j = 0; j < 8; j++) {
        int row = ob + to + j;
        float bo = bias[row];
        float4 rv = acc[j];
        rv.x += bo; rv.y += bo; rv.z += bo; rv.w += bo;
        *(float4*)(Y + (size_t)row*MTOT + m0 + tm) = rv;
    }
}

// ---------------- BN stats / apply / maxpool ----------------
__global__ void zero_stats_kernel(float* sum, float* ssq)
{
    int i = threadIdx.x;
    if (i < 3*128) { sum[i] = 0.f; ssq[i] = 0.f; }
}

__global__ __launch_bounds__(256)
void stats_kernel(const float* __restrict__ Y, float* __restrict__ sum, float* __restrict__ ssq)
{
    const int o = blockIdx.x >> 5;
    const int chunk = (blockIdx.x & 31) << 13;
    const float* p = Y + (size_t)o*MTOT + chunk;
    float s = 0.f, q = 0.f;
    for (int i = threadIdx.x; i < 8192; i += 256) {
        float v = __ldg(p+i);
        s += v; q += v*v;
    }
#pragma unroll
    for (int off = 16; off; off >>= 1) {
        s += __shfl_down_sync(~0u, s, off);
        q += __shfl_down_sync(~0u, q, off);
    }
    __shared__ float ws[8], wq[8];
    if ((threadIdx.x&31)==0) { ws[threadIdx.x>>5] = s; wq[threadIdx.x>>5] = q; }
    __syncthreads();
    if (threadIdx.x < 8) {
        s = ws[threadIdx.x]; q = wq[threadIdx.x];
#pragma unroll
        for (int off = 4; off; off >>= 1) {
            s += __shfl_down_sync(0xFFu, s, off);
            q += __shfl_down_sync(0xFFu, q, off);
        }
        if (threadIdx.x == 0) { atomicAdd(&sum[o], s); atomicAdd(&ssq[o], q); }
    }
}

__global__ __launch_bounds__(256)
void bn_relu_kernel(float* __restrict__ Y, const float* __restrict__ sum,
                    const float* __restrict__ ssq, const float* __restrict__ gamma,
                    const float* __restrict__ beta)
{
    const int o = blockIdx.x >> 8;
    const int base = (blockIdx.x & 255)*1024 + threadIdx.x*4;
    const float inv = 1.0f/(float)MTOT;
    float mean = sum[o]*inv;
    float var  = ssq[o]*inv - mean*mean;
    float sc = gamma[o]*rsqrtf(var + BN_EPS);
    float sh = beta[o] - sc*mean;
    float4* p = (float4*)(Y + (size_t)o*MTOT + base);
    float4 v = *p;
    v.x = fmaxf(fmaf(sc,v.x,sh),0.f); v.y = fmaxf(fmaf(sc,v.y,sh),0.f);
    v.z = fmaxf(fmaf(sc,v.z,sh),0.f); v.w = fmaxf(fmaf(sc,v.w,sh),0.f);
    *p = v;
}

__global__ __launch_bounds__(256)
void maxpool_kernel(const float* __restrict__ X, float* __restrict__ out)
{
    const int j = blockIdx.x*256 + threadIdx.x;
    const int b = j >> 17, o = (j >> 10) & 127, s = j & 1023;
    const float4* p = (const float4*)(X + (size_t)o*MTOT + ((size_t)(b*NS+s)<<5));
    float m = -__int_as_float(0x7f800000);
#pragma unroll
    for (int i = 0; i < 8; i++) {
        float4 v = p[i];
        m = fmaxf(m, fmaxf(fmaxf(v.x,v.y), fmaxf(v.z,v.w)));
    }
    out[j] = m;
}

// ---------------- host threefry for far0 ----------------
static inline uint32_t rotl32(uint32_t x, int d){ return (x<<d)|(x>>(32-d)); }
static void tf2x32(uint32_t k0, uint32_t k1, uint32_t x0, uint32_t x1,
                   uint32_t* o0, uint32_t* o1)
{
    uint32_t ks[3] = { k0, k1, k0^k1^0x1BD11BDAu };
    x0 += ks[0]; x1 += ks[1];
    static const int R[2][4] = { {13,15,26,6}, {17,29,16,24} };
    for (int g = 0; g < 5; g++) {
        const int* r = R[g&1];
        for (int i = 0; i < 4; i++) { x0 += x1; x1 = rotl32(x1, r[i]); x1 ^= x0; }
        x0 += ks[(g+1)%3];
        x1 += ks[(g+2)%3] + (uint32_t)(g+1);
    }
    *o0 = x0; *o1 = x1;
}
static void compute_far0(int* far)
{
    // jax.random.randint(key(42),(8,),0,16384), threefry_partitionable:
    // k2 = block(key,(0,1)); bits[i] = o0^o1 of block(k2,(0,i)); far = bits & 16383
    uint32_t ka, kb;
    tf2x32(0u, 42u, 0u, 1u, &ka, &kb);
    for (int i = 0; i < NB; i++) {
        uint32_t o0, o1;
        tf2x32(ka, kb, 0u, (uint32_t)i, &o0, &o1);
        far[i] = (int)((o0 ^ o1) & (NPTS - 1));
    }
}

extern "C" void kernel_launch(void* const* d_in, const int* in_sizes, int n_in,
                              void* d_out, int out_size)
{
    const float* xyz    = (const float*)d_in[0];
    const float* points = (const float*)d_in[1];
    const float* w0 = (const float*)d_in[2];
    const float* b0 = (const float*)d_in[3];
    const float* g0 = (const float*)d_in[4];
    const float* be0= (const float*)d_in[5];
    const float* w1 = (const float*)d_in[6];
    const float* b1 = (const float*)d_in[7];
    const float* g1 = (const float*)d_in[8];
    const float* be1= (const float*)d_in[9];
    const float* w2 = (const float*)d_in[10];
    const float* b2 = (const float*)d_in[11];
    const float* g2 = (const float*)d_in[12];
    const float* be2= (const float*)d_in[13];
    float* out = (float*)d_out;

    Far0 f; compute_far0(f.v);

    float *X0,*A,*Bf,*Y3,*nxyz,*sum,*ssq;
    cudaGetSymbolAddress((void**)&X0, g_X0);
    cudaGetSymbolAddress((void**)&A,  g_A);
    cudaGetSymbolAddress((void**)&Bf, g_Bf);
    cudaGetSymbolAddress((void**)&Y3, g_Y3);
    cudaGetSymbolAddress((void**)&nxyz, g_newxyz);
    cudaGetSymbolAddress((void**)&sum, g_sum);
    cudaGetSymbolAddress((void**)&ssq, g_ssq);

    const int FPS_SMEM = FPS_HALF*12;              // 98304
    const int KNN_SMEM = 65536 + 16384 + 8192;
    const int G67_SMEM = (NC0*64 + NC0*128)*4;
    const int G64_SMEM = (64*64 + 64*128)*4;
    cudaFuncSetAttribute(fps_kernel, cudaFuncAttributeMaxDynamicSharedMemorySize, FPS_SMEM);
    cudaFuncSetAttribute(knn_kernel, cudaFuncAttributeMaxDynamicSharedMemorySize, KNN_SMEM);
    cudaFuncSetAttribute(gemm_kernel<NC0>, cudaFuncAttributeMaxDynamicSharedMemorySize, G67_SMEM);
    cudaFuncSetAttribute(gemm_kernel<64>,  cudaFuncAttributeMaxDynamicSharedMemorySize, G64_SMEM);

    fps_kernel<<<NB*2, 1024, FPS_SMEM>>>(xyz, nxyz, out, f);
    knn_kernel<<<NB*NS, 128, KNN_SMEM>>>(xyz, points, nxyz, X0);

    zero_stats_kernel<<<1, 512>>>(sum, ssq);

    gemm_kernel<NC0><<<dim3(MTOT/128,1), 256, G67_SMEM>>>(X0, w0, b0, A);
    stats_kernel<<<64*32, 256>>>(A, sum+0, ssq+0);
    bn_relu_kernel<<<64*256, 256>>>(A, sum+0, ssq+0, g0, be0);

    gemm_kernel<64><<<dim3(MTOT/128,1), 256, G64_SMEM>>>(A, w1, b1, Bf);
    stats_kernel<<<64*32, 256>>>(Bf, sum+64, ssq+64);
    bn_relu_kernel<<<64*256, 256>>>(Bf, sum+64, ssq+64, g1, be1);

    gemm_kernel<64><<<dim3(MTOT/128,2), 256, G64_SMEM>>>(Bf, w2, b2, Y3);
    stats_kernel<<<128*32, 256>>>(Y3, sum+128, ssq+128);
    bn_relu_kernel<<<128*256, 256>>>(Y3, sum+128, ssq+128, g2, be2);

    maxpool_kernel<<<(NB*128*NS)/256, 256>>>(Y3, out + NB*3*NS);
}